// round 1
// baseline (speedup 1.0000x reference)
#include <cuda_runtime.h>
#include <cstdint>
#include <cstddef>

#define BATCH 64
#define HID   2048
#define GATE4 8192
#define IN_F  1024
#define MAX_T 160
#define BH    (BATCH*HID)

// Persistent device scratch (static allocation is the sanctioned path).
__device__ float g_h[2][2][BH];          // [layer][parity][B*H] ping-pong h state
__device__ float g_c[2][BH];             // [layer][B*H] cell state (in-place safe: per-CTA-private cols)
__device__ float g_xall[MAX_T + 1][BH];  // slot 0 = zeros; slot t+1 = x_next at step t

// ---------------- PTX helpers ----------------
__device__ __forceinline__ uint32_t f2tf32(float f) {
    uint32_t u;
    asm("cvt.rna.tf32.f32 %0, %1;" : "=r"(u) : "f"(f));
    return u;
}
__device__ __forceinline__ void cpa16(void* s, const void* g) {
    uint32_t sa = (uint32_t)__cvta_generic_to_shared(s);
    asm volatile("cp.async.cg.shared.global [%0], [%1], 16;" :: "r"(sa), "l"(g));
}
__device__ __forceinline__ void cp_commit() { asm volatile("cp.async.commit_group;"); }
__device__ __forceinline__ void cp_wait1()  { asm volatile("cp.async.wait_group 1;"); }

__device__ __forceinline__ void mma8(float* c,
                                     uint32_t a0, uint32_t a1, uint32_t a2, uint32_t a3,
                                     uint32_t b0, uint32_t b1) {
    asm volatile(
        "mma.sync.aligned.m16n8k8.row.col.f32.tf32.tf32.f32 "
        "{%0,%1,%2,%3}, {%4,%5,%6,%7}, {%8,%9}, {%0,%1,%2,%3};"
        : "+f"(c[0]), "+f"(c[1]), "+f"(c[2]), "+f"(c[3])
        : "r"(a0), "r"(a1), "r"(a2), "r"(a3), "r"(b0), "r"(b1));
}

__device__ __forceinline__ float sigmoidf_(float x) {
    return 1.0f / (1.0f + __expf(-x));
}

// ---------------- init: copy states, zero x slot 0 ----------------
__global__ __launch_bounds__(128) void init_kernel(const float* __restrict__ h0,
                                                   const float* __restrict__ c0) {
    int i = blockIdx.x * 128 + threadIdx.x;
    if (i >= BH) return;
    g_h[0][0][i] = h0[i];
    g_h[1][0][i] = h0[BH + i];
    g_c[0][i]    = c0[i];
    g_c[1][i]    = c0[BH + i];
    g_xall[0][i] = 0.0f;
}

// ---------------- fused LSTM gate GEMM + activation ----------------
// CTA b (0..127) owns hidden units [b*16, b*16+16) -> 64 gate rows (i,f,g,o x16).
// C[64 rows][64 batch] = Wcat @ [X|Hin]^T, K = 4096.  4 warps, each m32 x n32.
__global__ __launch_bounds__(128) void gate_kernel(
    const float* __restrict__ Wih, const float* __restrict__ Whh,
    const float* __restrict__ bih, const float* __restrict__ bhh,
    int layer, int t)
{
    __shared__ float pool[2][2][64][36];  // [stage][0=W,1=A][row][k] stride 36 (16B-aligned, conflict-free frags)

    const int tid  = threadIdx.x;
    const int lane = tid & 31, w = tid >> 5;
    const int wm = w & 1, wn = w >> 1;
    const int grp = lane >> 2, qt = lane & 3;
    const int jb = blockIdx.x * 16;
    const int p  = t & 1;

    const float* X    = (layer == 0) ? g_xall[t] : g_h[0][p ^ 1];
    const float* Hin  = g_h[layer][p];
    float*       Hout = g_h[layer][p ^ 1];
    float*       C    = g_c[layer];
    float*       Xout = (layer == 1) ? g_xall[t + 1] : nullptr;

    float acc[2][4][4];
#pragma unroll
    for (int a = 0; a < 2; a++)
#pragma unroll
        for (int b = 0; b < 4; b++)
#pragma unroll
            for (int cc = 0; cc < 4; cc++) acc[a][b][cc] = 0.0f;

    // prologue: chunk 0 (Wih / X, k0 = 0) -> stage 0
    {
#pragma unroll
        for (int i = 0; i < 4; i++) {
            int f = tid * 4 + i;
            int r = f >> 3, q = f & 7;
            int grow = ((r >> 4) * HID) + jb + (r & 15);
            cpa16(&pool[0][0][r][q * 4], Wih + (size_t)grow * HID + q * 4);
            cpa16(&pool[0][1][r][q * 4], X   + (size_t)r    * HID + q * 4);
        }
    }
    cp_commit();

    for (int kc = 0; kc < 128; ++kc) {
        if (kc + 1 < 128) {
            int kc2 = kc + 1;
            const float* Wsel = (kc2 < 64) ? Wih : Whh;
            const float* Asel = (kc2 < 64) ? X : Hin;
            int kk = (kc2 < 64) ? kc2 * 32 : (kc2 - 64) * 32;
            int st = kc2 & 1;
#pragma unroll
            for (int i = 0; i < 4; i++) {
                int f = tid * 4 + i;
                int r = f >> 3, q = f & 7;
                int grow = ((r >> 4) * HID) + jb + (r & 15);
                cpa16(&pool[st][0][r][q * 4], Wsel + (size_t)grow * HID + kk + q * 4);
                cpa16(&pool[st][1][r][q * 4], Asel + (size_t)r    * HID + kk + q * 4);
            }
        }
        cp_commit();
        cp_wait1();
        __syncthreads();

        const int st = kc & 1;
#pragma unroll
        for (int k8 = 0; k8 < 4; k8++) {
            const int kb = k8 * 8;
            uint32_t bf[4][2];
#pragma unroll
            for (int nt = 0; nt < 4; nt++) {
                int n = wn * 32 + nt * 8 + grp;
                bf[nt][0] = f2tf32(pool[st][1][n][kb + qt]);
                bf[nt][1] = f2tf32(pool[st][1][n][kb + qt + 4]);
            }
#pragma unroll
            for (int mt = 0; mt < 2; mt++) {
                int rb = wm * 32 + mt * 16 + grp;
                uint32_t a0 = f2tf32(pool[st][0][rb    ][kb + qt]);
                uint32_t a1 = f2tf32(pool[st][0][rb + 8][kb + qt]);
                uint32_t a2 = f2tf32(pool[st][0][rb    ][kb + qt + 4]);
                uint32_t a3 = f2tf32(pool[st][0][rb + 8][kb + qt + 4]);
#pragma unroll
                for (int nt = 0; nt < 4; nt++)
                    mma8(acc[mt][nt], a0, a1, a2, a3, bf[nt][0], bf[nt][1]);
            }
        }
        __syncthreads();
    }

    // ---- epilogue: fragments -> smem -> gate math -> state update ----
    float(*sC)[68] = reinterpret_cast<float(*)[68]>(&pool[0][0][0][0]);
#pragma unroll
    for (int mt = 0; mt < 2; mt++) {
        int r0 = wm * 32 + mt * 16 + grp;
#pragma unroll
        for (int nt = 0; nt < 4; nt++) {
            int c0 = wn * 32 + nt * 8 + qt * 2;
            sC[r0    ][c0    ] = acc[mt][nt][0];
            sC[r0    ][c0 + 1] = acc[mt][nt][1];
            sC[r0 + 8][c0    ] = acc[mt][nt][2];
            sC[r0 + 8][c0 + 1] = acc[mt][nt][3];
        }
    }
    __syncthreads();

    const int jt   = tid & 15;
    const int mb   = (tid >> 4) * 8;
    const int jcol = jb + jt;
    float bsum[4];
#pragma unroll
    for (int g = 0; g < 4; ++g) bsum[g] = bih[g * HID + jcol] + bhh[g * HID + jcol];

#pragma unroll
    for (int im = 0; im < 8; ++im) {
        int m = mb + im;
        float pi = sC[jt     ][m] + bsum[0];
        float pf = sC[16 + jt][m] + bsum[1];
        float pg = sC[32 + jt][m] + bsum[2];
        float po = sC[48 + jt][m] + bsum[3];
        float ig = sigmoidf_(pi);
        float fg = sigmoidf_(pf);
        float gg = tanhf(pg);
        float og = sigmoidf_(po);
        float cold = C[(size_t)m * HID + jcol];
        float cn = fg * cold + ig * gg;
        float hn = og * tanhf(cn);
        C[(size_t)m * HID + jcol]    = cn;
        Hout[(size_t)m * HID + jcol] = hn;
        if (Xout) Xout[(size_t)m * HID + jcol] = hn;
    }
}

// ---------------- batched reconstruction GEMM with time flip ----------------
// grid (IN_F/64, T): block (fx, y) computes out[T-1-y][0:64][fx*64 : fx*64+64]
//   = xall[y+1] @ Wrec^T + brec
__global__ __launch_bounds__(128) void recons_kernel(
    const float* __restrict__ Wrec, const float* __restrict__ brec,
    float* __restrict__ out, int T)
{
    __shared__ float pool[2][2][64][36];

    const int tid  = threadIdx.x;
    const int lane = tid & 31, w = tid >> 5;
    const int wm = w & 1, wn = w >> 1;
    const int grp = lane >> 2, qt = lane & 3;
    const int fb = blockIdx.x * 64;
    const int y  = blockIdx.y;
    const float* A = g_xall[y + 1];

    float acc[2][4][4];
#pragma unroll
    for (int a = 0; a < 2; a++)
#pragma unroll
        for (int b = 0; b < 4; b++)
#pragma unroll
            for (int cc = 0; cc < 4; cc++) acc[a][b][cc] = 0.0f;

    {
#pragma unroll
        for (int i = 0; i < 4; i++) {
            int f = tid * 4 + i;
            int r = f >> 3, q = f & 7;
            cpa16(&pool[0][0][r][q * 4], Wrec + (size_t)(fb + r) * HID + q * 4);
            cpa16(&pool[0][1][r][q * 4], A    + (size_t)r        * HID + q * 4);
        }
    }
    cp_commit();

    for (int kc = 0; kc < 64; ++kc) {
        if (kc + 1 < 64) {
            int kk = (kc + 1) * 32;
            int st = (kc + 1) & 1;
#pragma unroll
            for (int i = 0; i < 4; i++) {
                int f = tid * 4 + i;
                int r = f >> 3, q = f & 7;
                cpa16(&pool[st][0][r][q * 4], Wrec + (size_t)(fb + r) * HID + kk + q * 4);
                cpa16(&pool[st][1][r][q * 4], A    + (size_t)r        * HID + kk + q * 4);
            }
        }
        cp_commit();
        cp_wait1();
        __syncthreads();

        const int st = kc & 1;
#pragma unroll
        for (int k8 = 0; k8 < 4; k8++) {
            const int kb = k8 * 8;
            uint32_t bf[4][2];
#pragma unroll
            for (int nt = 0; nt < 4; nt++) {
                int n = wn * 32 + nt * 8 + grp;
                bf[nt][0] = f2tf32(pool[st][1][n][kb + qt]);
                bf[nt][1] = f2tf32(pool[st][1][n][kb + qt + 4]);
            }
#pragma unroll
            for (int mt = 0; mt < 2; mt++) {
                int rb = wm * 32 + mt * 16 + grp;
                uint32_t a0 = f2tf32(pool[st][0][rb    ][kb + qt]);
                uint32_t a1 = f2tf32(pool[st][0][rb + 8][kb + qt]);
                uint32_t a2 = f2tf32(pool[st][0][rb    ][kb + qt + 4]);
                uint32_t a3 = f2tf32(pool[st][0][rb + 8][kb + qt + 4]);
#pragma unroll
                for (int nt = 0; nt < 4; nt++)
                    mma8(acc[mt][nt], a0, a1, a2, a3, bf[nt][0], bf[nt][1]);
            }
        }
        __syncthreads();
    }

    float(*sC)[68] = reinterpret_cast<float(*)[68]>(&pool[0][0][0][0]);
#pragma unroll
    for (int mt = 0; mt < 2; mt++) {
        int r0 = wm * 32 + mt * 16 + grp;
#pragma unroll
        for (int nt = 0; nt < 4; nt++) {
            int c0 = wn * 32 + nt * 8 + qt * 2;
            sC[r0    ][c0    ] = acc[mt][nt][0];
            sC[r0    ][c0 + 1] = acc[mt][nt][1];
            sC[r0 + 8][c0    ] = acc[mt][nt][2];
            sC[r0 + 8][c0 + 1] = acc[mt][nt][3];
        }
    }
    __syncthreads();

    const int f  = tid & 63;
    const int mh = tid >> 6;
    const float bv = brec[fb + f];
#pragma unroll
    for (int im = 0; im < 32; ++im) {
        int m = mh * 32 + im;
        out[((size_t)(T - 1 - y) * BATCH + m) * IN_F + fb + f] = sC[f][m] + bv;
    }
}

// ---------------- launch ----------------
extern "C" void kernel_launch(void* const* d_in, const int* in_sizes, int n_in,
                              void* d_out, int out_size) {
    (void)in_sizes; (void)n_in;
    const float* h0   = (const float*)d_in[1];
    const float* c0   = (const float*)d_in[2];
    const float* Wih  = (const float*)d_in[3];
    const float* Whh  = (const float*)d_in[4];
    const float* bih  = (const float*)d_in[5];
    const float* bhh  = (const float*)d_in[6];
    const float* Wrec = (const float*)d_in[7];
    const float* brec = (const float*)d_in[8];
    float* out = (float*)d_out;

    int T = out_size / (BATCH * IN_F);   // seq_len lives on device; derive from out_size
    if (T < 1) T = 1;
    if (T > MAX_T) T = MAX_T;

    init_kernel<<<(BH + 127) / 128, 128>>>(h0, c0);

    const size_t WL = (size_t)GATE4 * HID;   // per-layer weight matrix stride
    for (int t = 0; t < T; ++t) {
        gate_kernel<<<128, 128>>>(Wih,      Whh,      bih,         bhh,         0, t);
        gate_kernel<<<128, 128>>>(Wih + WL, Whh + WL, bih + GATE4, bhh + GATE4, 1, t);
    }
    recons_kernel<<<dim3(IN_F / 64, T), 128>>>(Wrec, brec, out, T);
}

// round 3
// speedup vs baseline: 2.2903x; 2.2903x over previous
#include <cuda_runtime.h>
#include <cuda_fp16.h>
#include <cstdint>
#include <cstddef>

#define BATCH 64
#define HID   2048
#define GATE4 8192
#define IN_F  1024
#define MAX_T 160
#define BH    (BATCH*HID)
#define KC    64      // k-chunk size in halves
#define SROW  72      // smem row stride in halves (144B = 9*16B, conflict-free)

// -------- persistent device scratch (static allocation = sanctioned path) --------
__device__ __half g_w16[2][GATE4][2 * HID];    // per layer: rows = gate rows, cols = [W_ih | W_hh]
__device__ __half g_wrec16[IN_F][HID];
__device__ __half g_h16[2][2][BATCH * HID];    // [layer][parity] hidden state, fp16
__device__ float  g_c[2][BATCH * HID];         // cell state stays fp32
__device__ __half g_x16[MAX_T + 1][BATCH * HID]; // slot 0 = zeros, slot t+1 = layer-1 output at step t

// ---------------- PTX helpers ----------------
__device__ __forceinline__ void cpa16(void* s, const void* g) {
    uint32_t sa = (uint32_t)__cvta_generic_to_shared(s);
    asm volatile("cp.async.cg.shared.global [%0], [%1], 16;" :: "r"(sa), "l"(g));
}
__device__ __forceinline__ void cp_commit() { asm volatile("cp.async.commit_group;"); }
__device__ __forceinline__ void cp_wait1()  { asm volatile("cp.async.wait_group 1;"); }

__device__ __forceinline__ void mma16(float* c,
                                      uint32_t a0, uint32_t a1, uint32_t a2, uint32_t a3,
                                      uint32_t b0, uint32_t b1) {
    asm volatile(
        "mma.sync.aligned.m16n8k16.row.col.f32.f16.f16.f32 "
        "{%0,%1,%2,%3}, {%4,%5,%6,%7}, {%8,%9}, {%0,%1,%2,%3};"
        : "+f"(c[0]), "+f"(c[1]), "+f"(c[2]), "+f"(c[3])
        : "r"(a0), "r"(a1), "r"(a2), "r"(a3), "r"(b0), "r"(b1));
}

__device__ __forceinline__ float sigmoidf_(float x) {
    return 1.0f / (1.0f + __expf(-x));
}

// ---------------- one-time per-launch: fp32 -> fp16 weight conversion ----------------
__global__ __launch_bounds__(256) void convert_kernel(const float* __restrict__ Wih,
                                                      const float* __restrict__ Whh,
                                                      const float* __restrict__ Wrec) {
    const int C4 = HID / 4;                 // float4 units per 2048-col row
    const int N1 = 2 * GATE4 * C4;          // per weight-matrix set (both layers)
    const int N3 = IN_F * C4;
    const int total = 2 * N1 + N3;
    for (int i = blockIdx.x * 256 + threadIdx.x; i < total; i += gridDim.x * 256) {
        if (i < N1) {
            int l = i / (GATE4 * C4);
            int rem = i - l * GATE4 * C4;
            int row = rem / C4, c4 = rem % C4;
            float4 v = reinterpret_cast<const float4*>(Wih)[(size_t)(l * GATE4 + row) * C4 + c4];
            __half2* dst = reinterpret_cast<__half2*>(&g_w16[l][row][c4 * 4]);
            dst[0] = __floats2half2_rn(v.x, v.y);
            dst[1] = __floats2half2_rn(v.z, v.w);
        } else if (i < 2 * N1) {
            int j = i - N1;
            int l = j / (GATE4 * C4);
            int rem = j - l * GATE4 * C4;
            int row = rem / C4, c4 = rem % C4;
            float4 v = reinterpret_cast<const float4*>(Whh)[(size_t)(l * GATE4 + row) * C4 + c4];
            __half2* dst = reinterpret_cast<__half2*>(&g_w16[l][row][HID + c4 * 4]);
            dst[0] = __floats2half2_rn(v.x, v.y);
            dst[1] = __floats2half2_rn(v.z, v.w);
        } else {
            int j = i - 2 * N1;
            int row = j / C4, c4 = j % C4;
            float4 v = reinterpret_cast<const float4*>(Wrec)[(size_t)row * C4 + c4];
            __half2* dst = reinterpret_cast<__half2*>(&g_wrec16[row][c4 * 4]);
            dst[0] = __floats2half2_rn(v.x, v.y);
            dst[1] = __floats2half2_rn(v.z, v.w);
        }
    }
}

// ---------------- init: states -> device scratch ----------------
__global__ __launch_bounds__(256) void init_kernel(const float* __restrict__ h0,
                                                   const float* __restrict__ c0) {
    int i = blockIdx.x * 256 + threadIdx.x;
    if (i >= BH) return;
    g_h16[0][0][i] = __float2half_rn(h0[i]);
    g_h16[1][0][i] = __float2half_rn(h0[BH + i]);
    g_c[0][i] = c0[i];
    g_c[1][i] = c0[BH + i];
    g_x16[0][i] = __ushort_as_half(0);
}

// ---------------- fused LSTM gate GEMM + activation ----------------
// CTA b (0..127) owns 16 hidden units -> 64 gate rows (i,f,g,o x 16), all 64 batch cols.
// gates[64x64] = Wcombined[64 x 4096] @ [X|Hin]^T, fp16 mma m16n8k16, fp32 accum.
__global__ __launch_bounds__(256) void gate_kernel(const float* __restrict__ bih,
                                                   const float* __restrict__ bhh,
                                                   int layer, int t) {
    __shared__ __align__(16) __half smW[2][64][SROW];
    __shared__ __align__(16) __half smA[2][64][SROW];

    const int tid  = threadIdx.x;
    const int lane = tid & 31, w = tid >> 5;
    const int wm = w & 3, wn = w >> 2;          // 4 x 2 warp grid over m64 x n64
    const int grp = lane >> 2, qt = lane & 3;
    const int jb = blockIdx.x * 16;             // first hidden unit owned
    const int p  = t & 1;

    const __half* X    = (layer == 0) ? g_x16[t] : g_h16[0][p ^ 1];
    const __half* Hin  = g_h16[layer][p];
    __half*       Hout = g_h16[layer][p ^ 1];
    float*        C    = g_c[layer];
    __half*       Xout = (layer == 1) ? g_x16[t + 1] : nullptr;
    const __half* Wl   = &g_w16[layer][0][0];

    float acc[4][4];
#pragma unroll
    for (int s = 0; s < 4; s++)
#pragma unroll
        for (int cc = 0; cc < 4; cc++) acc[s][cc] = 0.0f;

    // loader: chunk kc (64 halves of K) into stage st
    auto load_chunk = [&](int kc, int st) {
        const __half* Asel = (kc < 32) ? X : Hin;
        const int acol = (kc & 31) * KC;
        const int wcol = kc * KC;
#pragma unroll
        for (int i = 0; i < 2; i++) {
            int idx = tid * 2 + i;              // 0..511
            int r = idx >> 3, q = idx & 7;      // row 0..63, 8 x 16B per row
            int R = (r >> 4) * HID + jb + (r & 15);   // gate-row -> global row
            cpa16(&smW[st][r][q * 8], Wl + (size_t)R * (2 * HID) + wcol + q * 8);
            cpa16(&smA[st][r][q * 8], Asel + (size_t)r * HID + acol + q * 8);
        }
    };

    load_chunk(0, 0);
    cp_commit();

    for (int kc = 0; kc < 64; ++kc) {
        if (kc < 63) load_chunk(kc + 1, (kc + 1) & 1);
        cp_commit();
        cp_wait1();
        __syncthreads();

        const int st = kc & 1;
        const uint32_t* Wp = reinterpret_cast<const uint32_t*>(&smW[st][0][0]);
        const uint32_t* Ap = reinterpret_cast<const uint32_t*>(&smA[st][0][0]);
        const int rA = wm * 16 + grp;
#pragma unroll
        for (int k16 = 0; k16 < 4; ++k16) {
            const int kb2 = k16 * 8 + qt;       // b32 index of (k16*16 + 2*qt)
            uint32_t a0 = Wp[rA * 36 + kb2];
            uint32_t a1 = Wp[(rA + 8) * 36 + kb2];
            uint32_t a2 = Wp[rA * 36 + kb2 + 4];
            uint32_t a3 = Wp[(rA + 8) * 36 + kb2 + 4];
#pragma unroll
            for (int sub = 0; sub < 4; ++sub) {
                const int n = wn * 32 + sub * 8 + grp;
                uint32_t b0 = Ap[n * 36 + kb2];
                uint32_t b1 = Ap[n * 36 + kb2 + 4];
                mma16(acc[sub], a0, a1, a2, a3, b0, b1);
            }
        }
        __syncthreads();
    }

    // ---- epilogue: fragments -> smem -> gate math -> state update ----
    float(*sC)[68] = reinterpret_cast<float(*)[68]>(&smW[0][0][0]);  // 64x68 f32 = 17.4KB, fits
#pragma unroll
    for (int sub = 0; sub < 4; ++sub) {
        const int c0 = wn * 32 + sub * 8 + 2 * qt;
        const int r0 = wm * 16 + grp;
        sC[r0][c0]     = acc[sub][0];
        sC[r0][c0 + 1] = acc[sub][1];
        sC[r0 + 8][c0]     = acc[sub][2];
        sC[r0 + 8][c0 + 1] = acc[sub][3];
    }
    __syncthreads();

    const int jt = tid & 15;          // unit within CTA
    const int mg = tid >> 4;          // 0..15, batch group of 4
    const int jcol = jb + jt;
    float bsum[4];
#pragma unroll
    for (int g = 0; g < 4; ++g) bsum[g] = bih[g * HID + jcol] + bhh[g * HID + jcol];

#pragma unroll
    for (int im = 0; im < 4; ++im) {
        const int m = mg * 4 + im;
        float pi = sC[jt][m]      + bsum[0];
        float pf = sC[16 + jt][m] + bsum[1];
        float pg = sC[32 + jt][m] + bsum[2];
        float po = sC[48 + jt][m] + bsum[3];
        float ig = sigmoidf_(pi);
        float fg = sigmoidf_(pf);
        float gg = tanhf(pg);
        float og = sigmoidf_(po);
        float cold = C[(size_t)m * HID + jcol];
        float cn = fg * cold + ig * gg;
        float hn = og * tanhf(cn);
        C[(size_t)m * HID + jcol] = cn;
        __half hn16 = __float2half_rn(hn);
        Hout[(size_t)m * HID + jcol] = hn16;
        if (Xout) Xout[(size_t)m * HID + jcol] = hn16;
    }
}

// ---------------- batched reconstruction GEMM with time flip ----------------
// block (fx, y): out[T-1-y][0:64][fx*64 .. +64] = x16[y+1] @ Wrec^T + brec
__global__ __launch_bounds__(256) void recons_kernel(const float* __restrict__ brec,
                                                     float* __restrict__ out, int T) {
    __shared__ __align__(16) __half smW[2][64][SROW];
    __shared__ __align__(16) __half smA[2][64][SROW];

    const int tid  = threadIdx.x;
    const int lane = tid & 31, w = tid >> 5;
    const int wm = w & 3, wn = w >> 2;
    const int grp = lane >> 2, qt = lane & 3;
    const int fb = blockIdx.x * 64;
    const int y  = blockIdx.y;
    const __half* A = g_x16[y + 1];
    const __half* Wr = &g_wrec16[0][0];

    float acc[4][4];
#pragma unroll
    for (int s = 0; s < 4; s++)
#pragma unroll
        for (int cc = 0; cc < 4; cc++) acc[s][cc] = 0.0f;

    auto load_chunk = [&](int kc, int st) {
        const int col = kc * KC;
#pragma unroll
        for (int i = 0; i < 2; i++) {
            int idx = tid * 2 + i;
            int r = idx >> 3, q = idx & 7;
            cpa16(&smW[st][r][q * 8], Wr + (size_t)(fb + r) * HID + col + q * 8);
            cpa16(&smA[st][r][q * 8], A + (size_t)r * HID + col + q * 8);
        }
    };

    load_chunk(0, 0);
    cp_commit();

    for (int kc = 0; kc < 32; ++kc) {
        if (kc < 31) load_chunk(kc + 1, (kc + 1) & 1);
        cp_commit();
        cp_wait1();
        __syncthreads();

        const int st = kc & 1;
        const uint32_t* Wp = reinterpret_cast<const uint32_t*>(&smW[st][0][0]);
        const uint32_t* Ap = reinterpret_cast<const uint32_t*>(&smA[st][0][0]);
        const int rA = wm * 16 + grp;
#pragma unroll
        for (int k16 = 0; k16 < 4; ++k16) {
            const int kb2 = k16 * 8 + qt;
            uint32_t a0 = Wp[rA * 36 + kb2];
            uint32_t a1 = Wp[(rA + 8) * 36 + kb2];
            uint32_t a2 = Wp[rA * 36 + kb2 + 4];
            uint32_t a3 = Wp[(rA + 8) * 36 + kb2 + 4];
#pragma unroll
            for (int sub = 0; sub < 4; ++sub) {
                const int n = wn * 32 + sub * 8 + grp;
                uint32_t b0 = Ap[n * 36 + kb2];
                uint32_t b1 = Ap[n * 36 + kb2 + 4];
                mma16(acc[sub], a0, a1, a2, a3, b0, b1);
            }
        }
        __syncthreads();
    }

    float(*sC)[68] = reinterpret_cast<float(*)[68]>(&smW[0][0][0]);
#pragma unroll
    for (int sub = 0; sub < 4; ++sub) {
        const int c0 = wn * 32 + sub * 8 + 2 * qt;
        const int r0 = wm * 16 + grp;
        sC[r0][c0]     = acc[sub][0];
        sC[r0][c0 + 1] = acc[sub][1];
        sC[r0 + 8][c0]     = acc[sub][2];
        sC[r0 + 8][c0 + 1] = acc[sub][3];
    }
    __syncthreads();

    const int f  = tid & 63;
    const int mh = tid >> 6;          // 0..3
    const float bv = brec[fb + f];
#pragma unroll
    for (int im = 0; im < 16; ++im) {
        const int m = mh * 16 + im;
        out[((size_t)(T - 1 - y) * BATCH + m) * IN_F + fb + f] = sC[f][m] + bv;
    }
}

// ---------------- launch ----------------
extern "C" void kernel_launch(void* const* d_in, const int* in_sizes, int n_in,
                              void* d_out, int out_size) {
    (void)in_sizes; (void)n_in;
    const float* h0   = (const float*)d_in[1];
    const float* c0   = (const float*)d_in[2];
    const float* Wih  = (const float*)d_in[3];
    const float* Whh  = (const float*)d_in[4];
    const float* bih  = (const float*)d_in[5];
    const float* bhh  = (const float*)d_in[6];
    const float* Wrec = (const float*)d_in[7];
    const float* brec = (const float*)d_in[8];
    float* out = (float*)d_out;

    int T = out_size / (BATCH * IN_F);
    if (T < 1) T = 1;
    if (T > MAX_T) T = MAX_T;

    convert_kernel<<<4096, 256>>>(Wih, Whh, Wrec);
    init_kernel<<<(BH + 255) / 256, 256>>>(h0, c0);

    for (int t = 0; t < T; ++t) {
        gate_kernel<<<128, 256>>>(bih,         bhh,         0, t);
        gate_kernel<<<128, 256>>>(bih + GATE4, bhh + GATE4, 1, t);
    }
    recons_kernel<<<dim3(IN_F / 64, T), 256>>>(brec, out, T);
}

// round 5
// speedup vs baseline: 2.6328x; 1.1496x over previous
#include <cuda_runtime.h>
#include <cuda_fp16.h>
#include <cstdint>
#include <cstddef>

#define BATCH 64
#define HID   2048
#define GATE4 8192
#define IN_F  1024
#define MAX_T 160
#define BH    (BATCH*HID)
#define KC    64      // k-chunk size in halves
#define SROW  72      // smem row stride in halves (144B = 9*16B, conflict-free)
#define STAGES 6      // cp.async pipeline depth (prefetch 5 ahead)
#define STAGE_HALVES (64 * SROW)
#define GATE_SMEM_BYTES (STAGES * STAGE_HALVES * 2 /*arrays*/ * 2 /*bytes*/)

// -------- persistent device scratch (static allocation = sanctioned path) --------
__device__ __half g_w16[2][GATE4][2 * HID];    // per layer: rows = gate rows, cols = [W_ih | W_hh]
__device__ __half g_wrec16[IN_F][HID];
__device__ __half g_h16[2][2][BATCH * HID];    // [layer][parity] hidden state, fp16
__device__ float  g_c[2][BATCH * HID];         // cell state stays fp32
__device__ __half g_x16[MAX_T + 1][BATCH * HID]; // slot 0 = zeros, slot t+1 = layer-1 output at step t

// ---------------- PTX helpers ----------------
__device__ __forceinline__ void cpa16(void* s, const void* g) {
    uint32_t sa = (uint32_t)__cvta_generic_to_shared(s);
    asm volatile("cp.async.cg.shared.global [%0], [%1], 16;" :: "r"(sa), "l"(g));
}
__device__ __forceinline__ void cp_commit() { asm volatile("cp.async.commit_group;"); }
template <int N>
__device__ __forceinline__ void cp_wait() { asm volatile("cp.async.wait_group %0;" :: "n"(N)); }

__device__ __forceinline__ void mma16(float* c,
                                      uint32_t a0, uint32_t a1, uint32_t a2, uint32_t a3,
                                      uint32_t b0, uint32_t b1) {
    asm volatile(
        "mma.sync.aligned.m16n8k16.row.col.f32.f16.f16.f32 "
        "{%0,%1,%2,%3}, {%4,%5,%6,%7}, {%8,%9}, {%0,%1,%2,%3};"
        : "+f"(c[0]), "+f"(c[1]), "+f"(c[2]), "+f"(c[3])
        : "r"(a0), "r"(a1), "r"(a2), "r"(a3), "r"(b0), "r"(b1));
}

__device__ __forceinline__ float sigmoidf_(float x) {
    return 1.0f / (1.0f + __expf(-x));
}

// ---------------- one-time per-launch: fp32 -> fp16 weight conversion ----------------
__global__ __launch_bounds__(256) void convert_kernel(const float* __restrict__ Wih,
                                                      const float* __restrict__ Whh,
                                                      const float* __restrict__ Wrec) {
    const int C4 = HID / 4;
    const int N1 = 2 * GATE4 * C4;
    const int N3 = IN_F * C4;
    const int total = 2 * N1 + N3;
    for (int i = blockIdx.x * 256 + threadIdx.x; i < total; i += gridDim.x * 256) {
        if (i < N1) {
            int l = i / (GATE4 * C4);
            int rem = i - l * GATE4 * C4;
            int row = rem / C4, c4 = rem % C4;
            float4 v = reinterpret_cast<const float4*>(Wih)[(size_t)(l * GATE4 + row) * C4 + c4];
            __half2* dst = reinterpret_cast<__half2*>(&g_w16[l][row][c4 * 4]);
            dst[0] = __floats2half2_rn(v.x, v.y);
            dst[1] = __floats2half2_rn(v.z, v.w);
        } else if (i < 2 * N1) {
            int j = i - N1;
            int l = j / (GATE4 * C4);
            int rem = j - l * GATE4 * C4;
            int row = rem / C4, c4 = rem % C4;
            float4 v = reinterpret_cast<const float4*>(Whh)[(size_t)(l * GATE4 + row) * C4 + c4];
            __half2* dst = reinterpret_cast<__half2*>(&g_w16[l][row][HID + c4 * 4]);
            dst[0] = __floats2half2_rn(v.x, v.y);
            dst[1] = __floats2half2_rn(v.z, v.w);
        } else {
            int j = i - 2 * N1;
            int row = j / C4, c4 = j % C4;
            float4 v = reinterpret_cast<const float4*>(Wrec)[(size_t)row * C4 + c4];
            __half2* dst = reinterpret_cast<__half2*>(&g_wrec16[row][c4 * 4]);
            dst[0] = __floats2half2_rn(v.x, v.y);
            dst[1] = __floats2half2_rn(v.z, v.w);
        }
    }
}

// ---------------- init: states -> device scratch ----------------
__global__ __launch_bounds__(256) void init_kernel(const float* __restrict__ h0,
                                                   const float* __restrict__ c0) {
    int i = blockIdx.x * 256 + threadIdx.x;
    if (i >= BH) return;
    g_h16[0][0][i] = __float2half_rn(h0[i]);
    g_h16[1][0][i] = __float2half_rn(h0[BH + i]);
    g_c[0][i] = c0[i];
    g_c[1][i] = c0[BH + i];
    g_x16[0][i] = __ushort_as_half(0);
}

// ---------------- fused LSTM gate GEMM + activation ----------------
// CTA b (0..127) owns 16 hidden units -> 64 gate rows (i,f,g,o x 16), all 64 batch cols.
// gates[64x64] = Wcombined[64 x 4096] @ [X|Hin]^T, fp16 mma m16n8k16, fp32 accum.
// 6-stage cp.async pipeline (prefetch 5 chunks ahead) to cover DRAM latency.
__global__ __launch_bounds__(256) void gate_kernel(const float* __restrict__ bih,
                                                   const float* __restrict__ bhh,
                                                   int layer, int t) {
    extern __shared__ __align__(16) __half dyn_smem[];
    __half* smW = dyn_smem;                          // [STAGES][64][SROW]
    __half* smA = dyn_smem + STAGES * STAGE_HALVES;  // [STAGES][64][SROW]

    const int tid  = threadIdx.x;
    const int lane = tid & 31, w = tid >> 5;
    const int wm = w & 3, wn = w >> 2;          // 4 x 2 warp grid over m64 x n64
    const int grp = lane >> 2, qt = lane & 3;
    const int jb = blockIdx.x * 16;             // first hidden unit owned
    const int p  = t & 1;

    const __half* X    = (layer == 0) ? g_x16[t] : g_h16[0][p ^ 1];
    const __half* Hin  = g_h16[layer][p];
    __half*       Hout = g_h16[layer][p ^ 1];
    float*        C    = g_c[layer];
    __half*       Xout = (layer == 1) ? g_x16[t + 1] : nullptr;
    const __half* Wl   = &g_w16[layer][0][0];

    float acc[4][4];
#pragma unroll
    for (int s = 0; s < 4; s++)
#pragma unroll
        for (int cc = 0; cc < 4; cc++) acc[s][cc] = 0.0f;

    // per-thread load coords: thread covers 2 (row, 16B-quad) slots
    const int idx0 = tid * 2;
    const int r0_ = idx0 >> 3, q0_ = idx0 & 7;
    const int r1_ = (idx0 + 1) >> 3, q1_ = (idx0 + 1) & 7;
    const int R0 = (r0_ >> 4) * HID + jb + (r0_ & 15);
    const int R1 = (r1_ >> 4) * HID + jb + (r1_ & 15);

    auto load_chunk = [&](int kc, int st) {
        const __half* Asel = (kc < 32) ? X : Hin;
        const int acol = (kc & 31) * KC;
        const int wcol = kc * KC;
        __half* w_base = smW + st * STAGE_HALVES;
        __half* a_base = smA + st * STAGE_HALVES;
        cpa16(w_base + r0_ * SROW + q0_ * 8, Wl + (size_t)R0 * (2 * HID) + wcol + q0_ * 8);
        cpa16(a_base + r0_ * SROW + q0_ * 8, Asel + (size_t)r0_ * HID + acol + q0_ * 8);
        cpa16(w_base + r1_ * SROW + q1_ * 8, Wl + (size_t)R1 * (2 * HID) + wcol + q1_ * 8);
        cpa16(a_base + r1_ * SROW + q1_ * 8, Asel + (size_t)r1_ * HID + acol + q1_ * 8);
    };

    // prologue: chunks 0..4 into stages 0..4
#pragma unroll
    for (int k = 0; k < STAGES - 1; ++k) {
        load_chunk(k, k);
        cp_commit();
    }

    int st = 0, ld = STAGES - 1;  // consume stage, load stage
    for (int kc = 0; kc < 64; ++kc) {
        if (kc + STAGES - 1 < 64) load_chunk(kc + STAGES - 1, ld);
        cp_commit();
        cp_wait<STAGES - 1>();   // all but the 5 newest groups done -> chunk kc arrived
        __syncthreads();

        const uint32_t* Wp = reinterpret_cast<const uint32_t*>(smW + st * STAGE_HALVES);
        const uint32_t* Ap = reinterpret_cast<const uint32_t*>(smA + st * STAGE_HALVES);
        const int rA = wm * 16 + grp;
#pragma unroll
        for (int k16 = 0; k16 < 4; ++k16) {
            const int kb2 = k16 * 8 + qt;       // b32 index of (k16*16 + 2*qt)
            uint32_t a0 = Wp[rA * 36 + kb2];
            uint32_t a1 = Wp[(rA + 8) * 36 + kb2];
            uint32_t a2 = Wp[rA * 36 + kb2 + 4];
            uint32_t a3 = Wp[(rA + 8) * 36 + kb2 + 4];
#pragma unroll
            for (int sub = 0; sub < 4; ++sub) {
                const int n = wn * 32 + sub * 8 + grp;
                uint32_t b0 = Ap[n * 36 + kb2];
                uint32_t b1 = Ap[n * 36 + kb2 + 4];
                mma16(acc[sub], a0, a1, a2, a3, b0, b1);
            }
        }
        __syncthreads();   // protects stage 'st' (reloaded next iteration as 'ld')

        st = (st == STAGES - 1) ? 0 : st + 1;
        ld = (ld == STAGES - 1) ? 0 : ld + 1;
    }

    // ---- epilogue: fragments -> smem -> gate math -> state update ----
    float(*sC)[68] = reinterpret_cast<float(*)[68]>(dyn_smem);  // 64x68 f32 = 17.4KB
#pragma unroll
    for (int sub = 0; sub < 4; ++sub) {
        const int c0 = wn * 32 + sub * 8 + 2 * qt;
        const int r0 = wm * 16 + grp;
        sC[r0][c0]     = acc[sub][0];
        sC[r0][c0 + 1] = acc[sub][1];
        sC[r0 + 8][c0]     = acc[sub][2];
        sC[r0 + 8][c0 + 1] = acc[sub][3];
    }
    __syncthreads();

    const int jt = tid & 15;          // unit within CTA
    const int mg = tid >> 4;          // 0..15, batch group of 4
    const int jcol = jb + jt;
    float bsum[4];
#pragma unroll
    for (int g = 0; g < 4; ++g) bsum[g] = bih[g * HID + jcol] + bhh[g * HID + jcol];

#pragma unroll
    for (int im = 0; im < 4; ++im) {
        const int m = mg * 4 + im;
        float pi = sC[jt][m]      + bsum[0];
        float pf = sC[16 + jt][m] + bsum[1];
        float pg = sC[32 + jt][m] + bsum[2];
        float po = sC[48 + jt][m] + bsum[3];
        float ig = sigmoidf_(pi);
        float fg = sigmoidf_(pf);
        float gg = tanhf(pg);
        float og = sigmoidf_(po);
        float cold = C[(size_t)m * HID + jcol];
        float cn = fg * cold + ig * gg;
        float hn = og * tanhf(cn);
        C[(size_t)m * HID + jcol] = cn;
        __half hn16 = __float2half_rn(hn);
        Hout[(size_t)m * HID + jcol] = hn16;
        if (Xout) Xout[(size_t)m * HID + jcol] = hn16;
    }
}

// ---------------- batched reconstruction GEMM with time flip ----------------
// block (fx, y): out[T-1-y][0:64][fx*64 .. +64] = x16[y+1] @ Wrec^T + brec
__global__ __launch_bounds__(256) void recons_kernel(const float* __restrict__ brec,
                                                     float* __restrict__ out, int T) {
    __shared__ __align__(16) __half smW[2][64][SROW];
    __shared__ __align__(16) __half smA[2][64][SROW];

    const int tid  = threadIdx.x;
    const int lane = tid & 31, w = tid >> 5;
    const int wm = w & 3, wn = w >> 2;
    const int grp = lane >> 2, qt = lane & 3;
    const int fb = blockIdx.x * 64;
    const int y  = blockIdx.y;
    const __half* A = g_x16[y + 1];
    const __half* Wr = &g_wrec16[0][0];

    float acc[4][4];
#pragma unroll
    for (int s = 0; s < 4; s++)
#pragma unroll
        for (int cc = 0; cc < 4; cc++) acc[s][cc] = 0.0f;

    auto load_chunk = [&](int kc, int st) {
        const int col = kc * KC;
#pragma unroll
        for (int i = 0; i < 2; i++) {
            int idx = tid * 2 + i;
            int r = idx >> 3, q = idx & 7;
            cpa16(&smW[st][r][q * 8], Wr + (size_t)(fb + r) * HID + col + q * 8);
            cpa16(&smA[st][r][q * 8], A + (size_t)r * HID + col + q * 8);
        }
    };

    load_chunk(0, 0);
    cp_commit();

    for (int kc = 0; kc < 32; ++kc) {
        if (kc < 31) load_chunk(kc + 1, (kc + 1) & 1);
        cp_commit();
        cp_wait<1>();
        __syncthreads();

        const int st = kc & 1;
        const uint32_t* Wp = reinterpret_cast<const uint32_t*>(&smW[st][0][0]);
        const uint32_t* Ap = reinterpret_cast<const uint32_t*>(&smA[st][0][0]);
        const int rA = wm * 16 + grp;
#pragma unroll
        for (int k16 = 0; k16 < 4; ++k16) {
            const int kb2 = k16 * 8 + qt;
            uint32_t a0 = Wp[rA * 36 + kb2];
            uint32_t a1 = Wp[(rA + 8) * 36 + kb2];
            uint32_t a2 = Wp[rA * 36 + kb2 + 4];
            uint32_t a3 = Wp[(rA + 8) * 36 + kb2 + 4];
#pragma unroll
            for (int sub = 0; sub < 4; ++sub) {
                const int n = wn * 32 + sub * 8 + grp;
                uint32_t b0 = Ap[n * 36 + kb2];
                uint32_t b1 = Ap[n * 36 + kb2 + 4];
                mma16(acc[sub], a0, a1, a2, a3, b0, b1);
            }
        }
        __syncthreads();
    }

    float(*sC)[68] = reinterpret_cast<float(*)[68]>(&smW[0][0][0]);
#pragma unroll
    for (int sub = 0; sub < 4; ++sub) {
        const int c0 = wn * 32 + sub * 8 + 2 * qt;
        const int r0 = wm * 16 + grp;
        sC[r0][c0]     = acc[sub][0];
        sC[r0][c0 + 1] = acc[sub][1];
        sC[r0 + 8][c0]     = acc[sub][2];
        sC[r0 + 8][c0 + 1] = acc[sub][3];
    }
    __syncthreads();

    const int f  = tid & 63;
    const int mh = tid >> 6;          // 0..3
    const float bv = brec[fb + f];
#pragma unroll
    for (int im = 0; im < 16; ++im) {
        const int m = mh * 16 + im;
        out[((size_t)(T - 1 - y) * BATCH + m) * IN_F + fb + f] = sC[f][m] + bv;
    }
}

// ---------------- launch ----------------
extern "C" void kernel_launch(void* const* d_in, const int* in_sizes, int n_in,
                              void* d_out, int out_size) {
    (void)in_sizes; (void)n_in;
    const float* h0   = (const float*)d_in[1];
    const float* c0   = (const float*)d_in[2];
    const float* Wih  = (const float*)d_in[3];
    const float* Whh  = (const float*)d_in[4];
    const float* bih  = (const float*)d_in[5];
    const float* bhh  = (const float*)d_in[6];
    const float* Wrec = (const float*)d_in[7];
    const float* brec = (const float*)d_in[8];
    float* out = (float*)d_out;

    int T = out_size / (BATCH * IN_F);
    if (T < 1) T = 1;
    if (T > MAX_T) T = MAX_T;

    // Raise dynamic smem limit for the 6-stage pipeline (immediate host-side
    // attribute set; idempotent, not a graph node, not an allocation).
    cudaFuncSetAttribute(gate_kernel, cudaFuncAttributeMaxDynamicSharedMemorySize,
                         GATE_SMEM_BYTES);

    convert_kernel<<<4096, 256>>>(Wih, Whh, Wrec);
    init_kernel<<<(BH + 255) / 256, 256>>>(h0, c0);

    for (int t = 0; t < T; ++t) {
        gate_kernel<<<128, 256, GATE_SMEM_BYTES>>>(bih,         bhh,         0, t);
        gate_kernel<<<128, 256, GATE_SMEM_BYTES>>>(bih + GATE4, bhh + GATE4, 1, t);
    }
    recons_kernel<<<dim3(IN_F / 64, T), 256>>>(brec, out, T);
}

// round 7
// speedup vs baseline: 3.7415x; 1.4211x over previous
#include <cuda_runtime.h>
#include <cuda_fp16.h>
#include <cstdint>
#include <cstddef>

#define BATCH 64
#define HID   2048
#define GATE4 8192
#define IN_F  1024
#define MAX_T 160
#define BH    (BATCH*HID)      // fp32 state elements per layer
#define BHH   131072           // halves per activation snapshot (= 32 chunks * 4096)
#define STAGES 4
#define STAGE_HALVES 16384     // per stage: W 8192 halves + A 8192 halves (32KB)
#define DSMEM_BYTES (STAGES * STAGE_HALVES * 2)   // 131072 B

// -------- persistent device scratch (static allocation = sanctioned path) --------
// Weights re-tiled per-CTA, per-64-col-K-chunk, SW128-swizzled, contiguous 8KB tiles.
__device__ __half g_w16c[2][128][64 * 4096];     // [layer][cta][kchunk*4096 + r*64 + swz]
__device__ __half g_wrec16c[16][32 * 4096];      // [fx][kchunk*4096 + r*64 + swz]
__device__ __half g_h16c[2][2][BHH];             // [layer][parity] chunked+swizzled h
__device__ float  g_c[2][BH];                    // cell state, linear fp32
__device__ __half g_x16c[(size_t)(MAX_T + 1) * BHH]; // chunked+swizzled x snapshots

// ---------------- PTX helpers ----------------
__device__ __forceinline__ uint32_t s2u(const void* p) {
    return (uint32_t)__cvta_generic_to_shared(p);
}
__device__ __forceinline__ void mbar_init(uint32_t a, uint32_t cnt) {
    asm volatile("mbarrier.init.shared.b64 [%0], %1;" :: "r"(a), "r"(cnt) : "memory");
}
__device__ __forceinline__ void mbar_expect(uint32_t a, uint32_t tx) {
    asm volatile("mbarrier.arrive.expect_tx.shared.b64 _, [%0], %1;" :: "r"(a), "r"(tx) : "memory");
}
__device__ __forceinline__ void mbar_wait(uint32_t a, uint32_t ph) {
    asm volatile(
        "{\n\t.reg .pred P;\n\t"
        "WL%=:\n\t"
        "mbarrier.try_wait.parity.acquire.cta.shared::cta.b64 P, [%0], %1;\n\t"
        "@P bra WD%=;\n\t"
        "bra WL%=;\n\t"
        "WD%=:\n\t}"
        :: "r"(a), "r"(ph) : "memory");
}
__device__ __forceinline__ void cp_bulk(uint32_t smem_dst, const void* gmem_src,
                                        uint32_t bytes, uint32_t mbar) {
    asm volatile(
        "cp.async.bulk.shared::cta.global.mbarrier::complete_tx::bytes [%0], [%1], %2, [%3];"
        :: "r"(smem_dst), "l"(gmem_src), "r"(bytes), "r"(mbar) : "memory");
}
__device__ __forceinline__ void fence_async() {
    asm volatile("fence.proxy.async.shared::cta;" ::: "memory");
}
__device__ __forceinline__ void mma16(float* c,
                                      uint32_t a0, uint32_t a1, uint32_t a2, uint32_t a3,
                                      uint32_t b0, uint32_t b1) {
    asm volatile(
        "mma.sync.aligned.m16n8k16.row.col.f32.f16.f16.f32 "
        "{%0,%1,%2,%3}, {%4,%5,%6,%7}, {%8,%9}, {%0,%1,%2,%3};"
        : "+f"(c[0]), "+f"(c[1]), "+f"(c[2]), "+f"(c[3])
        : "r"(a0), "r"(a1), "r"(a2), "r"(a3), "r"(b0), "r"(b1));
}
__device__ __forceinline__ float sigmoidf_(float x) {
    return 1.0f / (1.0f + __expf(-x));
}
// chunked+swizzled half offset for activation element (batch m, hidden j)
__device__ __forceinline__ size_t act_off(int m, int j) {
    int cc = j & 63;
    return (size_t)(j >> 6) * 4096 + m * 64 + (((cc >> 3) ^ (m & 7)) << 3) + (cc & 7);
}

// ---------------- one-time: fp32 weights -> fp16 chunked swizzled tiles ----------------
#define NWU (2 * 128 * 64 * 64 * 8)   // 16B units in gate weights
#define NRU (16 * 32 * 64 * 8)        // 16B units in recons weights
__global__ __launch_bounds__(256) void convert_kernel(const float* __restrict__ Wih,
                                                      const float* __restrict__ Whh,
                                                      const float* __restrict__ Wrec) {
    const int total = NWU + NRU;
    for (int i = blockIdx.x * 256 + threadIdx.x; i < total; i += gridDim.x * 256) {
        const float* src;
        __half* dst;
        if (i < NWU) {
            int u  = i & 7;
            int r  = (i >> 3) & 63;
            int kc = (i >> 9) & 63;
            int b  = (i >> 15) & 127;
            int l  = (i >> 22) & 1;
            int grow = (r >> 4) * HID + b * 16 + (r & 15);
            if (kc < 32)
                src = Wih + ((size_t)l * GATE4 + grow) * HID + kc * 64 + u * 8;
            else
                src = Whh + ((size_t)l * GATE4 + grow) * HID + (kc - 32) * 64 + u * 8;
            dst = &g_w16c[l][b][0] + (size_t)kc * 4096 + r * 64 + ((u ^ (r & 7)) << 3);
        } else {
            int j  = i - NWU;
            int u  = j & 7;
            int r  = (j >> 3) & 63;
            int kc = (j >> 9) & 31;
            int fx = (j >> 14) & 15;
            src = Wrec + (size_t)(fx * 64 + r) * HID + kc * 64 + u * 8;
            dst = &g_wrec16c[fx][0] + (size_t)kc * 4096 + r * 64 + ((u ^ (r & 7)) << 3);
        }
        float4 v0 = reinterpret_cast<const float4*>(src)[0];
        float4 v1 = reinterpret_cast<const float4*>(src)[1];
        __half2 h0 = __floats2half2_rn(v0.x, v0.y);
        __half2 h1 = __floats2half2_rn(v0.z, v0.w);
        __half2 h2 = __floats2half2_rn(v1.x, v1.y);
        __half2 h3 = __floats2half2_rn(v1.z, v1.w);
        uint4 o;
        o.x = *reinterpret_cast<uint32_t*>(&h0);
        o.y = *reinterpret_cast<uint32_t*>(&h1);
        o.z = *reinterpret_cast<uint32_t*>(&h2);
        o.w = *reinterpret_cast<uint32_t*>(&h3);
        *reinterpret_cast<uint4*>(dst) = o;
    }
}

// ---------------- init: states -> chunked scratch ----------------
__global__ __launch_bounds__(256) void init_kernel(const float* __restrict__ h0,
                                                   const float* __restrict__ c0) {
    int i = blockIdx.x * 256 + threadIdx.x;
    if (i >= BH) return;
    int m = i / HID, j = i % HID;
    size_t o = act_off(m, j);
    g_h16c[0][0][o] = __float2half_rn(h0[i]);
    g_h16c[1][0][o] = __float2half_rn(h0[BH + i]);
    g_c[0][i] = c0[i];
    g_c[1][i] = c0[BH + i];
    g_x16c[o] = __ushort_as_half(0);
}

// ---------------- fused LSTM gate GEMM + activation ----------------
// CTA b owns 16 hidden units -> 64 gate rows, all 64 batch cols. K = 4096 halves,
// consumed as 32 stage-iterations of 128 halves (two 64-half swizzled subtiles).
// Tiles arrive via cp.async.bulk (2 x 16KB per stage) + mbarrier; zero per-thread copies.
__global__ __launch_bounds__(256) void gate_kernel(const float* __restrict__ bih,
                                                   const float* __restrict__ bhh,
                                                   int layer, int t) {
    extern __shared__ __align__(16) __half dsm[];
    __shared__ __align__(8) uint64_t mbar[STAGES];

    const int tid  = threadIdx.x;
    const int lane = tid & 31, w = tid >> 5;
    const int wm = w & 3, wn = w >> 2;          // 4 x 2 warp grid over m64 x n64
    const int grp = lane >> 2, qt = lane & 3;
    const int jb = blockIdx.x * 16;
    const int p  = t & 1;

    const __half* Xc   = (layer == 0) ? g_x16c + (size_t)t * BHH : g_h16c[0][p ^ 1];
    const __half* Hinc = g_h16c[layer][p];
    __half*       Houtc = g_h16c[layer][p ^ 1];
    float*        C     = g_c[layer];
    __half*       Xoutc = (layer == 1) ? g_x16c + (size_t)(t + 1) * BHH : nullptr;
    const __half* Wc    = &g_w16c[layer][blockIdx.x][0];

    const uint32_t mb0 = s2u(&mbar[0]);
    if (tid == 0) {
#pragma unroll
        for (int s = 0; s < STAGES; ++s) mbar_init(mb0 + s * 8, 1);
        fence_async();
    }
    __syncthreads();

    const uint32_t dsm0 = s2u(dsm);
    auto issue = [&](int js) {
        const int ts = js & 3;
        const uint32_t m = mb0 + ts * 8;
        mbar_expect(m, 2 * 16384);
        cp_bulk(dsm0 + ts * STAGE_HALVES * 2, Wc + (size_t)js * 8192, 16384, m);
        const __half* As = (js < 16) ? Xc + (size_t)js * 8192 : Hinc + (size_t)(js - 16) * 8192;
        cp_bulk(dsm0 + ts * STAGE_HALVES * 2 + 16384, As, 16384, m);
    };
    if (tid == 0) { issue(0); issue(1); issue(2); }

    float acc[4][4];
#pragma unroll
    for (int s = 0; s < 4; s++)
#pragma unroll
        for (int cc = 0; cc < 4; cc++) acc[s][cc] = 0.0f;

    const int rA = wm * 16 + grp;
    for (int js = 0; js < 32; ++js) {
        if (tid == 0 && js + 3 < 32) issue(js + 3);
        const int ts = js & 3;
        mbar_wait(mb0 + ts * 8, (js >> 2) & 1);

        const uint32_t* Wp0 = reinterpret_cast<const uint32_t*>(dsm + ts * STAGE_HALVES);
        const uint32_t* Ap0 = Wp0 + 4096;
#pragma unroll
        for (int sub = 0; sub < 2; ++sub) {
            const uint32_t* Wp = Wp0 + sub * 2048;
            const uint32_t* Ap = Ap0 + sub * 2048;
#pragma unroll
            for (int k16 = 0; k16 < 4; ++k16) {
                const int su0 = (((2 * k16)     ^ grp) << 2) + qt;  // b32 idx of k-halves [16k16, +8)
                const int su1 = (((2 * k16 + 1) ^ grp) << 2) + qt;  // b32 idx of k-halves [16k16+8, +8)
                uint32_t a0 = Wp[rA * 32 + su0];
                uint32_t a1 = Wp[(rA + 8) * 32 + su0];
                uint32_t a2 = Wp[rA * 32 + su1];
                uint32_t a3 = Wp[(rA + 8) * 32 + su1];
#pragma unroll
                for (int s8 = 0; s8 < 4; ++s8) {
                    const int n = wn * 32 + s8 * 8 + grp;
                    uint32_t b0 = Ap[n * 32 + su0];
                    uint32_t b1 = Ap[n * 32 + su1];
                    mma16(acc[s8], a0, a1, a2, a3, b0, b1);
                }
            }
        }
        __syncthreads();   // all consumers done with stage ts before it is refilled
    }

    // ---- epilogue: fragments -> smem -> gate math -> state update ----
    float(*sC)[68] = reinterpret_cast<float(*)[68]>(dsm);  // 64x68 f32 = 17.4KB
#pragma unroll
    for (int s8 = 0; s8 < 4; ++s8) {
        const int c0 = wn * 32 + s8 * 8 + 2 * qt;
        const int r0 = wm * 16 + grp;
        sC[r0][c0]     = acc[s8][0];
        sC[r0][c0 + 1] = acc[s8][1];
        sC[r0 + 8][c0]     = acc[s8][2];
        sC[r0 + 8][c0 + 1] = acc[s8][3];
    }
    __syncthreads();

    const int jt = tid & 15;
    const int mg = tid >> 4;
    const int jcol = jb + jt;
    float bsum[4];
#pragma unroll
    for (int g = 0; g < 4; ++g) bsum[g] = bih[g * HID + jcol] + bhh[g * HID + jcol];

#pragma unroll
    for (int im = 0; im < 4; ++im) {
        const int m = mg * 4 + im;
        float pi = sC[jt][m]      + bsum[0];
        float pf = sC[16 + jt][m] + bsum[1];
        float pg = sC[32 + jt][m] + bsum[2];
        float po = sC[48 + jt][m] + bsum[3];
        float ig = sigmoidf_(pi);
        float fg = sigmoidf_(pf);
        float gg = tanhf(pg);
        float og = sigmoidf_(po);
        float cold = C[(size_t)m * HID + jcol];
        float cn = fg * cold + ig * gg;
        float hn = og * tanhf(cn);
        C[(size_t)m * HID + jcol] = cn;
        __half hn16 = __float2half_rn(hn);
        size_t o = act_off(m, jcol);
        Houtc[o] = hn16;
        if (Xoutc) Xoutc[o] = hn16;
    }
}

// ---------------- batched reconstruction GEMM with time flip ----------------
// block (fx, y): out[T-1-y][0:64][fx*64 .. +64] = x[y+1] @ Wrec^T + brec. K = 2048.
__global__ __launch_bounds__(256) void recons_kernel(const float* __restrict__ brec,
                                                     float* __restrict__ out, int T) {
    extern __shared__ __align__(16) __half dsm[];
    __shared__ __align__(8) uint64_t mbar[STAGES];

    const int tid  = threadIdx.x;
    const int lane = tid & 31, w = tid >> 5;
    const int wm = w & 3, wn = w >> 2;
    const int grp = lane >> 2, qt = lane & 3;
    const int fx = blockIdx.x;
    const int y  = blockIdx.y;
    const __half* Ac = g_x16c + (size_t)(y + 1) * BHH;
    const __half* Wc = &g_wrec16c[fx][0];

    const uint32_t mb0 = s2u(&mbar[0]);
    if (tid == 0) {
#pragma unroll
        for (int s = 0; s < STAGES; ++s) mbar_init(mb0 + s * 8, 1);
        fence_async();
    }
    __syncthreads();

    const uint32_t dsm0 = s2u(dsm);
    auto issue = [&](int js) {
        const int ts = js & 3;
        const uint32_t m = mb0 + ts * 8;
        mbar_expect(m, 2 * 16384);
        cp_bulk(dsm0 + ts * STAGE_HALVES * 2, Wc + (size_t)js * 8192, 16384, m);
        cp_bulk(dsm0 + ts * STAGE_HALVES * 2 + 16384, Ac + (size_t)js * 8192, 16384, m);
    };
    if (tid == 0) { issue(0); issue(1); issue(2); }

    float acc[4][4];
#pragma unroll
    for (int s = 0; s < 4; s++)
#pragma unroll
        for (int cc = 0; cc < 4; cc++) acc[s][cc] = 0.0f;

    const int rA = wm * 16 + grp;
    for (int js = 0; js < 16; ++js) {
        if (tid == 0 && js + 3 < 16) issue(js + 3);
        const int ts = js & 3;
        mbar_wait(mb0 + ts * 8, (js >> 2) & 1);

        const uint32_t* Wp0 = reinterpret_cast<const uint32_t*>(dsm + ts * STAGE_HALVES);
        const uint32_t* Ap0 = Wp0 + 4096;
#pragma unroll
        for (int sub = 0; sub < 2; ++sub) {
            const uint32_t* Wp = Wp0 + sub * 2048;
            const uint32_t* Ap = Ap0 + sub * 2048;
#pragma unroll
            for (int k16 = 0; k16 < 4; ++k16) {
                const int su0 = (((2 * k16)     ^ grp) << 2) + qt;
                const int su1 = (((2 * k16 + 1) ^ grp) << 2) + qt;
                uint32_t a0 = Wp[rA * 32 + su0];
                uint32_t a1 = Wp[(rA + 8) * 32 + su0];
                uint32_t a2 = Wp[rA * 32 + su1];
                uint32_t a3 = Wp[(rA + 8) * 32 + su1];
#pragma unroll
                for (int s8 = 0; s8 < 4; ++s8) {
                    const int n = wn * 32 + s8 * 8 + grp;
                    uint32_t b0 = Ap[n * 32 + su0];
                    uint32_t b1 = Ap[n * 32 + su1];
                    mma16(acc[s8], a0, a1, a2, a3, b0, b1);
                }
            }
        }
        __syncthreads();
    }

    float(*sC)[68] = reinterpret_cast<float(*)[68]>(dsm);
#pragma unroll
    for (int s8 = 0; s8 < 4; ++s8) {
        const int c0 = wn * 32 + s8 * 8 + 2 * qt;
        const int r0 = wm * 16 + grp;
        sC[r0][c0]     = acc[s8][0];
        sC[r0][c0 + 1] = acc[s8][1];
        sC[r0 + 8][c0]     = acc[s8][2];
        sC[r0 + 8][c0 + 1] = acc[s8][3];
    }
    __syncthreads();

    const int f  = tid & 63;
    const int mh = tid >> 6;
    const float bv = brec[fx * 64 + f];
#pragma unroll
    for (int im = 0; im < 16; ++im) {
        const int m = mh * 16 + im;
        out[((size_t)(T - 1 - y) * BATCH + m) * IN_F + fx * 64 + f] = sC[f][m] + bv;
    }
}

// ---------------- launch ----------------
extern "C" void kernel_launch(void* const* d_in, const int* in_sizes, int n_in,
                              void* d_out, int out_size) {
    (void)in_sizes; (void)n_in;
    const float* h0   = (const float*)d_in[1];
    const float* c0   = (const float*)d_in[2];
    const float* Wih  = (const float*)d_in[3];
    const float* Whh  = (const float*)d_in[4];
    const float* bih  = (const float*)d_in[5];
    const float* bhh  = (const float*)d_in[6];
    const float* Wrec = (const float*)d_in[7];
    const float* brec = (const float*)d_in[8];
    float* out = (float*)d_out;

    int T = out_size / (BATCH * IN_F);
    if (T < 1) T = 1;
    if (T > MAX_T) T = MAX_T;

    cudaFuncSetAttribute(gate_kernel, cudaFuncAttributeMaxDynamicSharedMemorySize,
                         DSMEM_BYTES);
    cudaFuncSetAttribute(recons_kernel, cudaFuncAttributeMaxDynamicSharedMemorySize,
                         DSMEM_BYTES);

    convert_kernel<<<4096, 256>>>(Wih, Whh, Wrec);
    init_kernel<<<(BH + 255) / 256, 256>>>(h0, c0);

    for (int t = 0; t < T; ++t) {
        gate_kernel<<<128, 256, DSMEM_BYTES>>>(bih,         bhh,         0, t);
        gate_kernel<<<128, 256, DSMEM_BYTES>>>(bih + GATE4, bhh + GATE4, 1, t);
    }
    recons_kernel<<<dim3(16, T), 256, DSMEM_BYTES>>>(brec, out, T);
}